// round 15
// baseline (speedup 1.0000x reference)
#include <cuda_runtime.h>
#include <cuda_fp16.h>
#include <cstdint>

#define NB 128
#define NC 500
#define HWD 16
#define HW 256
#define NPIX (NB*HW)          // 32768
#define C1 300
#define C1P 320               // padded channels for fp16 NHWC y1
#define C2 100
#define NTC 112               // padded N for tensor-core conv2 (14 n8-tiles)

// ---------------- device scratch (no allocations allowed) ----------------
__device__ float  g_l1[NC];
__device__ __half g_wl1h[NC*16*C1];       // [c][kk][co] fp16, pre-scaled by l1
__device__ int    g_seln[NPIX];
__device__ short  g_selc[NPIX*30];
__device__ float  g_self[NPIX*30];
__device__ __half g_y1h[(size_t)NB*34*34*C1P];  // NHWC fp16, padded to 320
__device__ __half g_w2h[9*NTC*C1P];             // [slab][c2p][c1p] fp16
__device__ __half g_y2h[(size_t)NB*36*36*C2];   // NHWC fp16
__device__ float  g_w3m[9*C2*3];                // [dy][dx][c1][c3]

// ================= baseline-PTX helpers =================
__device__ __forceinline__ uint32_t smem_u32(const void* p) {
    uint32_t a;
    asm("{ .reg .u64 t; cvta.to.shared.u64 t, %1; cvt.u32.u64 %0, t; }"
        : "=r"(a) : "l"(p));
    return a;
}
#define SWZ128(x) ((x) ^ (((x) >> 3) & 0x70))

__device__ __forceinline__ void cpa16(uint32_t dst, const void* src, int sz) {
    asm volatile("cp.async.cg.shared.global [%0], [%1], 16, %2;"
                 :: "r"(dst), "l"(src), "r"(sz));
}
__device__ __forceinline__ void cpa_commit() {
    asm volatile("cp.async.commit_group;");
}
__device__ __forceinline__ void ldsm4(uint32_t* r, uint32_t addr) {
    asm volatile("ldmatrix.sync.aligned.m8n8.x4.shared.b16 {%0,%1,%2,%3}, [%4];"
        : "=r"(r[0]), "=r"(r[1]), "=r"(r[2]), "=r"(r[3]) : "r"(addr));
}
__device__ __forceinline__ void mma16816(float* c, const uint32_t* a,
                                         uint32_t b0, uint32_t b1) {
    asm volatile("mma.sync.aligned.m16n8k16.row.col.f32.f16.f16.f32 "
        "{%0,%1,%2,%3}, {%4,%5,%6,%7}, {%8,%9}, {%0,%1,%2,%3};"
        : "+f"(c[0]), "+f"(c[1]), "+f"(c[2]), "+f"(c[3])
        : "r"(a[0]), "r"(a[1]), "r"(a[2]), "r"(a[3]), "r"(b0), "r"(b1));
}

// ---------------- consolidated prep: l1 + wl1h + w2h + w3m ----------------
#define W2H_BLKS ((9*NTC*C1P + 255)/256)
#define W3M_BLKS ((9*C2*3 + 255)/256)
__global__ __launch_bounds__(256) void k_prep(const float* __restrict__ phi,
                                              const float* __restrict__ w1,
                                              const float* __restrict__ w2,
                                              const float* __restrict__ w3) {
    int blk = blockIdx.x;
    int tid = threadIdx.x;
    if (blk < NC) {
        __shared__ float red[256];
        int c = blk;
        float s = 0.f;
        for (int d = tid; d < 192; d += 256) s += fabsf(phi[d*NC + c]);
        red[tid] = s;
        __syncthreads();
        for (int off = 128; off; off >>= 1) {
            if (tid < off) red[tid] += red[tid + off];
            __syncthreads();
        }
        float l1 = red[0] + 1e-12f;
        if (tid == 0) g_l1[c] = l1;
        for (int i = tid; i < 16*C1; i += 256) {
            int kk = i / C1, co = i % C1;
            g_wl1h[(c*16 + kk)*C1 + co] = __float2half(l1 * w1[(c*C1 + co)*16 + kk]);
        }
    } else if (blk < NC + W2H_BLKS) {
        int e = (blk - NC)*256 + tid;
        if (e < 9*NTC*C1P) {
            int c1 = e % C1P;
            int t  = e / C1P;
            int c2 = t % NTC;
            int dd = t / NTC;
            int dy = dd / 3, dx = dd % 3;
            float v = (c1 < C1 && c2 < C2) ? w2[((c1*C2 + c2)*3 + dy)*3 + dx] : 0.f;
            g_w2h[e] = __float2half(v);
        }
    } else {
        int e = (blk - NC - W2H_BLKS)*256 + tid;
        if (e < 9*C2*3) {
            int c3 = e % 3;
            int t  = e / 3;
            int c1 = t % C2;
            int dd = t / C2;
            int dy = dd / 3, dx = dd % 3;
            g_w3m[e] = w3[((c1*3 + c3)*3 + dy)*3 + dx];
        }
    }
}

// ---------------- fused transpose + top-30 + saturation ----------------
#define TOPK_SMEM ((NC*33 + NC)*4)
__global__ __launch_bounds__(256) void k_topk(const float* __restrict__ x,
                                              const float* __restrict__ jump_ptr) {
    extern __shared__ float sm[];
    float* sx  = sm;            // [500][33]
    float* sl1 = sm + NC*33;    // [500]

    int b   = blockIdx.y;
    int hw0 = blockIdx.x * 32;
    int tid = threadIdx.x;
    const float* xb = x + ((size_t)b*NC)*HW + hw0;

    for (int i = tid; i < NC*8; i += 256) {
        int c = i >> 3, j = i & 7;
        float4 v = *(const float4*)(xb + c*HW + j*4);
        float* d = sx + c*33 + j*4;
        d[0] = v.x; d[1] = v.y; d[2] = v.z; d[3] = v.w;
    }
    for (int i = tid; i < NC; i += 256) sl1[i] = g_l1[i];
    __syncthreads();

    float jump = *jump_ptr;
    int wid = tid >> 5, lane = tid & 31;

    for (int q = 0; q < 4; q++) {
        int p   = wid*4 + q;
        int pix = b*HW + hw0 + p;

        unsigned u[16];
        #pragma unroll
        for (int t = 0; t < 16; t++) {
            int c = lane + t*32;
            u[t] = (c < NC) ? (__float_as_uint(sx[c*33 + p]) & 0x7fffffffu) : 0u;
        }

        int n = 0;
        for (int it = 0; it < 30; it++) {
            unsigned a0 = max(u[0], u[1]),  a1 = max(u[2], u[3]);
            unsigned a2 = max(u[4], u[5]),  a3 = max(u[6], u[7]);
            unsigned a4 = max(u[8], u[9]),  a5 = max(u[10], u[11]);
            unsigned a6 = max(u[12], u[13]), a7 = max(u[14], u[15]);
            unsigned b0 = max(a0, a1), b1 = max(a2, a3);
            unsigned b2 = max(a4, a5), b3 = max(a6, a7);
            unsigned lm = max(max(b0, b1), max(b2, b3));

            unsigned gm = __reduce_max_sync(0xffffffffu, lm);
            unsigned ball = __ballot_sync(0xffffffffu, lm == gm);
            int leader = __ffs(ball) - 1;
            int c_sel = 0;
            if (lane == leader) {
                int mi = 0;
                #pragma unroll
                for (int t = 15; t >= 0; t--)
                    if (u[t] == gm) { mi = t; u[t] = 0u; }
                c_sel = lane + mi*32;
            }
            c_sel = __shfl_sync(0xffffffffu, c_sel, leader);

            float xv = sx[c_sel*33 + p];
            float th = jump * sl1[c_sel];
            float coef = 0.5f * ((float)((xv > th) - (xv < th)) +
                                 (float)((xv > -th) - (xv < -th)));
            if (coef != 0.f) {
                if (lane == 0) {
                    g_selc[pix*30 + n] = (short)c_sel;
                    g_self[pix*30 + n] = coef;
                }
                n++;
            }
        }
        if (lane == 0) g_seln[pix] = n;
    }
}

// ---------------- conv1 (sparse gather, fp16 table) -> y1h fp16 NHWC/320 ----------------
__global__ __launch_bounds__(160) void k_conv1(const float* __restrict__ b1) {
    __shared__ int   s_cnt;
    __shared__ int   s_pix[4], s_kk[4], s_n[4];
    __shared__ short s_ch[4][32];
    __shared__ float s_cf[4][32];

    int b   = blockIdx.y;
    int oy  = blockIdx.x / 34;
    int ox  = blockIdx.x % 34;
    int tid = threadIdx.x;

    if (tid == 0) {
        int cnt = 0;
        int p = oy & 1, q = ox & 1;
        for (int kh = p; kh < 4; kh += 2) {
            int iy2 = oy - kh; if (iy2 < 0) continue;
            int iy = iy2 >> 1; if (iy >= HWD) continue;
            for (int kw = q; kw < 4; kw += 2) {
                int ix2 = ox - kw; if (ix2 < 0) continue;
                int ix = ix2 >> 1; if (ix >= HWD) continue;
                int pix = (b*HWD + iy)*HWD + ix;
                s_pix[cnt] = pix;
                s_kk[cnt]  = kh*4 + kw;
                s_n[cnt]   = g_seln[pix];
                cnt++;
            }
        }
        s_cnt = cnt;
    }
    __syncthreads();
    int cnt = s_cnt;
    if (tid < 128) {
        int s = tid >> 5, t = tid & 31;
        if (s < cnt && t < s_n[s]) {
            s_ch[s][t] = g_selc[s_pix[s]*30 + t];
            s_cf[s][t] = g_self[s_pix[s]*30 + t];
        }
    }
    __syncthreads();

    size_t obase = ((size_t)(b*1156 + oy*34 + ox))*C1P;
    int t2 = tid;
    if (t2 < 150) {
        float ax0 = 0.f, ay0 = 0.f, ax1 = 0.f, ay1 = 0.f;
        const __half2* wtab = (const __half2*)g_wl1h;
        for (int s = 0; s < cnt; s++) {
            int kk = s_kk[s];
            int ns = s_n[s];
            int t = 0;
            #pragma unroll 2
            for (; t + 1 < ns; t += 2) {
                int ca = (int)s_ch[s][t];
                int cb = (int)s_ch[s][t+1];
                float cfa = s_cf[s][t];
                float cfb = s_cf[s][t+1];
                float2 wa = __half22float2(wtab[(ca*16 + kk)*150 + t2]);
                float2 wb = __half22float2(wtab[(cb*16 + kk)*150 + t2]);
                ax0 = fmaf(cfa, wa.x, ax0);
                ay0 = fmaf(cfa, wa.y, ay0);
                ax1 = fmaf(cfb, wb.x, ax1);
                ay1 = fmaf(cfb, wb.y, ay1);
            }
            if (t < ns) {
                int ca = (int)s_ch[s][t];
                float cfa = s_cf[s][t];
                float2 wa = __half22float2(wtab[(ca*16 + kk)*150 + t2]);
                ax0 = fmaf(cfa, wa.x, ax0);
                ay0 = fmaf(cfa, wa.y, ay0);
            }
        }
        int co = 2*t2;
        float ox2 = fmaxf((ax0 + ax1) + b1[co],   0.f);
        float oy2 = fmaxf((ay0 + ay1) + b1[co+1], 0.f);
        ((__half2*)(g_y1h + obase))[t2] = __floats2half2_rn(ox2, oy2);
    } else {
        ((__half2*)(g_y1h + obase))[t2] = __floats2half2_rn(0.f, 0.f);
    }
}

// ---------------- conv2: fp16 HMMA implicit GEMM, asym M32xN64/N48 tiles ---
// M=128 pixels/CTA, N=112 (c2 padded), K = 9 slabs * 320 ch, chunks of 64
// 3-stage cp.async pipeline, one barrier per chunk, hoisted geometry.
#define STAGE_BYTES 30720
__global__ __launch_bounds__(256, 2) void k_conv2_mma(const float* __restrict__ b2) {
    extern __shared__ char dsm[];
    uint32_t smu = smem_u32(dsm);

    int tid = threadIdx.x;
    int wid = tid >> 5;
    int lane = tid & 31;
    int mg = wid >> 1;        // 0..3 : rows mg*32..+32
    int ng = wid & 1;         // 0: cols 0..63 (4 n16), 1: cols 64..111 (3 n16)
    int b  = blockIdx.y;
    int p0 = blockIdx.x * 128;

    // ---- hoisted per-thread cp.async geometry (loop-invariant) ----
    int jj = tid & 7;
    int rr = tid >> 3;
    int oyk[4], oxk[4], gbase[4];
    uint32_t dstk[4];
    bool pok[4];
    #pragma unroll
    for (int k = 0; k < 4; k++) {
        int r = rr + k*32;
        int p = p0 + r;
        int oy = p / 36, ox = p - oy*36;
        oyk[k] = oy; oxk[k] = ox;
        pok[k] = (p < 1296);
        gbase[k] = ((b*34 + oy)*34 + ox)*C1P + jj*8;
        dstk[k]  = SWZ128(r*128 + jj*16);
    }

    float acc[2][8][4];
    #pragma unroll
    for (int mt = 0; mt < 2; mt++)
        #pragma unroll
        for (int nt = 0; nt < 8; nt++)
            #pragma unroll
            for (int j = 0; j < 4; j++) acc[mt][nt][j] = 0.f;

    int arow0 = mg*32 +      (lane & 15);
    int arow1 = mg*32 + 16 + (lane & 15);
    int acolb = (lane >> 4) * 16;
    int bn  = (lane & 7) + ((lane >> 4) & 1) * 8;
    int bkb = ((lane >> 3) & 1) * 16;

    auto issue = [&](int i) {
        int s = i % 3;
        int slab = i / 5;
        int c0 = (i - slab*5) * 64;
        int dy = slab / 3, dx = slab - dy*3;
        int shift = (dy*34 + dx)*C1P - c0;
        uint32_t abase = smu + (uint32_t)s * STAGE_BYTES;
        uint32_t bbase = abase + 16384u;
        #pragma unroll
        for (int k = 0; k < 4; k++) {
            bool val = pok[k] & (oyk[k] >= dy) & (oyk[k] < 34 + dy)
                              & (oxk[k] >= dx) & (oxk[k] < 34 + dx);
            size_t goff = val ? (size_t)(gbase[k] - shift) : 0;
            cpa16(abase + dstk[k], g_y1h + goff, val ? 16 : 0);
        }
        const __half* wbase = g_w2h + slab*(NTC*C1P) + c0 + jj*8;
        #pragma unroll
        for (int k = 0; k < 4; k++) {
            int r = rr + k*32;
            if (r < NTC)
                cpa16(bbase + dstk[k], wbase + r*C1P, 16);
        }
        cpa_commit();
    };

    auto compute = [&](int s) {
        uint32_t abase = smu + (uint32_t)s * STAGE_BYTES;
        uint32_t bbase = abase + 16384u;
        #pragma unroll
        for (int ks = 0; ks < 4; ks++) {
            uint32_t a0[4], a1[4];
            ldsm4(a0, abase + SWZ128(arow0*128 + ks*32 + acolb));
            ldsm4(a1, abase + SWZ128(arow1*128 + ks*32 + acolb));
            if (ng == 0) {
                #pragma unroll
                for (int nt = 0; nt < 4; nt++) {
                    uint32_t bf[4];
                    ldsm4(bf, bbase + SWZ128((nt*16 + bn)*128 + ks*32 + bkb));
                    mma16816(acc[0][nt*2],     a0, bf[0], bf[1]);
                    mma16816(acc[0][nt*2 + 1], a0, bf[2], bf[3]);
                    mma16816(acc[1][nt*2],     a1, bf[0], bf[1]);
                    mma16816(acc[1][nt*2 + 1], a1, bf[2], bf[3]);
                }
            } else {
                #pragma unroll
                for (int nt = 0; nt < 3; nt++) {
                    uint32_t bf[4];
                    ldsm4(bf, bbase + SWZ128((64 + nt*16 + bn)*128 + ks*32 + bkb));
                    mma16816(acc[0][nt*2],     a0, bf[0], bf[1]);
                    mma16816(acc[0][nt*2 + 1], a0, bf[2], bf[3]);
                    mma16816(acc[1][nt*2],     a1, bf[0], bf[1]);
                    mma16816(acc[1][nt*2 + 1], a1, bf[2], bf[3]);
                }
            }
        }
    };

    issue(0);
    issue(1);
    for (int i = 0; i < 45; i++) {
        if (i <= 43) asm volatile("cp.async.wait_group 1;" ::: "memory");
        else         asm volatile("cp.async.wait_group 0;" ::: "memory");
        __syncthreads();
        compute(i % 3);
        if (i <= 42) issue(i + 2);
    }

    // epilogue: bias + relu + store fp16 NHWC
    int g  = lane >> 2;
    int qp = (lane & 3) * 2;
    int ntmax = (ng == 0) ? 8 : 6;
    #pragma unroll
    for (int mt = 0; mt < 2; mt++) {
        int rbase = p0 + mg*32 + mt*16 + g;
        for (int nt = 0; nt < ntmax; nt++) {
            int n = ng*64 + nt*8 + qp;
            if (n < 100) {
                float b0v = b2[n], b1v = b2[n + 1];
                if (rbase < 1296) {
                    float o0 = fmaxf(acc[mt][nt][0] + b0v, 0.f);
                    float o1 = fmaxf(acc[mt][nt][1] + b1v, 0.f);
                    *(__half2*)&g_y2h[((size_t)b*1296 + rbase)*C2 + n] =
                        __floats2half2_rn(o0, o1);
                }
                if (rbase + 8 < 1296) {
                    float o0 = fmaxf(acc[mt][nt][2] + b0v, 0.f);
                    float o1 = fmaxf(acc[mt][nt][3] + b1v, 0.f);
                    *(__half2*)&g_y2h[((size_t)b*1296 + rbase + 8)*C2 + n] =
                        __floats2half2_rn(o0, o1);
                }
            }
        }
    }
}

// ---------------- conv3 (100->3 3x3 transpose) + ReLU + center crop -------
#define CONV3_SMEM ((3*35*100 + 9*C2*3)*4)
__global__ __launch_bounds__(96) void k_conv3(const float* __restrict__ b3,
                                              float* __restrict__ out) {
    extern __shared__ float cs[];
    float* s_y2 = cs;                 // [3][35][100] f32
    float* s_w3 = cs + 3*35*100;      // [c3][dy][dx][100]

    int u   = blockIdx.x;
    int b   = blockIdx.y;
    int tid = threadIdx.x;
    int v   = tid % 32;
    int c3  = tid / 32;

    for (int i = tid; i < 9*C2*3; i += 96) {
        int c1 = i % C2;
        int t  = i / C2;
        int dd = t % 9;
        int cc = t / 9;
        s_w3[(cc*9 + dd)*C2 + c1] = g_w3m[(dd*C2 + c1)*3 + cc];
    }
    {
        const __half2* src = (const __half2*)g_y2h;
        for (int i = tid; i < 3*35*50; i += 96) {
            int cl = i % 50;
            int t  = i / 50;
            int ix = t % 35;
            int r  = t / 35;
            float2 vv = __half22float2(
                src[(((size_t)b*1296 + (u+1+r)*36 + (ix+1))*C2 >> 1) + cl]);
            s_y2[(r*35 + ix)*100 + cl*2]     = vv.x;
            s_y2[(r*35 + ix)*100 + cl*2 + 1] = vv.y;
        }
    }
    __syncthreads();

    float acc = 0.f;
    #pragma unroll
    for (int dy = 0; dy < 3; dy++) {
        int r = 2 - dy;
        #pragma unroll
        for (int dx = 0; dx < 3; dx++) {
            int col = v + 2 - dx;
            const float4* yrow = (const float4*)(s_y2 + (r*35 + col)*100);
            const float4* wrow = (const float4*)(s_w3 + (c3*9 + dy*3 + dx)*C2);
            #pragma unroll 5
            for (int c = 0; c < 25; c++) {
                float4 yv = yrow[c];
                float4 wv = wrow[c];
                acc = fmaf(yv.x, wv.x, acc);
                acc = fmaf(yv.y, wv.y, acc);
                acc = fmaf(yv.z, wv.z, acc);
                acc = fmaf(yv.w, wv.w, acc);
            }
        }
    }
    out[((b*3 + c3)*32 + u)*32 + v] = fmaxf(acc + b3[c3], 0.f);
}

// ---------------- launch ----------------
extern "C" void kernel_launch(void* const* d_in, const int* in_sizes, int n_in,
                              void* d_out, int out_size) {
    const float* x    = (const float*)d_in[0];
    const float* phi  = (const float*)d_in[1];
    const float* jump = (const float*)d_in[2];
    const float* w1   = (const float*)d_in[3];
    const float* b1   = (const float*)d_in[4];
    const float* w2   = (const float*)d_in[5];
    const float* b2   = (const float*)d_in[6];
    const float* w3   = (const float*)d_in[7];
    const float* b3   = (const float*)d_in[8];
    float* out = (float*)d_out;

    cudaFuncSetAttribute(k_conv2_mma, cudaFuncAttributeMaxDynamicSharedMemorySize,
                         3*STAGE_BYTES);
    cudaFuncSetAttribute(k_conv2_mma, cudaFuncAttributePreferredSharedMemoryCarveout,
                         100);
    cudaFuncSetAttribute(k_topk, cudaFuncAttributeMaxDynamicSharedMemorySize,
                         TOPK_SMEM);
    cudaFuncSetAttribute(k_conv3, cudaFuncAttributeMaxDynamicSharedMemorySize,
                         CONV3_SMEM);

    k_prep<<<NC + W2H_BLKS + W3M_BLKS, 256>>>(phi, w1, w2, w3);   // 0
    k_topk<<<dim3(8, NB), 256, TOPK_SMEM>>>(x, jump);             // 1
    k_conv1<<<dim3(34*34, NB), 160>>>(b1);                        // 2
    k_conv2_mma<<<dim3(11, NB), 256, 3*STAGE_BYTES>>>(b2);        // 3  <- profiled slot
    k_conv3<<<dim3(32, NB), 96, CONV3_SMEM>>>(b3, out);           // 4
}

// round 16
// speedup vs baseline: 1.0625x; 1.0625x over previous
#include <cuda_runtime.h>
#include <cuda_fp16.h>
#include <cstdint>

#define NB 128
#define NC 500
#define HWD 16
#define HW 256
#define NPIX (NB*HW)          // 32768
#define C1 300
#define C1P 320               // padded channels for fp16 NHWC y1
#define C2 100
#define NTC 128               // padded N for tensor-core conv2 (16 n8-tiles)

// ---------------- device scratch (no allocations allowed) ----------------
__device__ float  g_l1[NC];
__device__ __half g_wl1h[NC*16*C1];       // [c][kk][co] fp16, pre-scaled by l1
__device__ int    g_seln[NPIX];
__device__ short  g_selc[NPIX*30];
__device__ float  g_self[NPIX*30];
__device__ __half g_y1h[(size_t)NB*34*34*C1P];  // NHWC fp16, padded to 320
__device__ __half g_w2h[9*NTC*C1P];             // [slab][c2p][c1p] fp16
__device__ __half g_y2h[(size_t)NB*36*36*C2];   // NHWC fp16
__device__ float  g_w3m[9*C2*3];                // [dy][dx][c1][c3]

// ================= baseline-PTX helpers =================
__device__ __forceinline__ uint32_t smem_u32(const void* p) {
    uint32_t a;
    asm("{ .reg .u64 t; cvta.to.shared.u64 t, %1; cvt.u32.u64 %0, t; }"
        : "=r"(a) : "l"(p));
    return a;
}
#define SWZ128(x) ((x) ^ (((x) >> 3) & 0x70))

__device__ __forceinline__ void cpa16(uint32_t dst, const void* src, int sz) {
    asm volatile("cp.async.cg.shared.global [%0], [%1], 16, %2;"
                 :: "r"(dst), "l"(src), "r"(sz));
}
__device__ __forceinline__ void cpa_commit() {
    asm volatile("cp.async.commit_group;");
}
__device__ __forceinline__ void ldsm4(uint32_t* r, uint32_t addr) {
    asm volatile("ldmatrix.sync.aligned.m8n8.x4.shared.b16 {%0,%1,%2,%3}, [%4];"
        : "=r"(r[0]), "=r"(r[1]), "=r"(r[2]), "=r"(r[3]) : "r"(addr));
}
__device__ __forceinline__ void mma16816(float* c, const uint32_t* a,
                                         uint32_t b0, uint32_t b1) {
    asm volatile("mma.sync.aligned.m16n8k16.row.col.f32.f16.f16.f32 "
        "{%0,%1,%2,%3}, {%4,%5,%6,%7}, {%8,%9}, {%0,%1,%2,%3};"
        : "+f"(c[0]), "+f"(c[1]), "+f"(c[2]), "+f"(c[3])
        : "r"(a[0]), "r"(a[1]), "r"(a[2]), "r"(a[3]), "r"(b0), "r"(b1));
}

// ---------------- consolidated prep: l1 + wl1h + w2h + w3m ----------------
#define W2H_BLKS ((9*NTC*C1P + 255)/256)
#define W3M_BLKS ((9*C2*3 + 255)/256)
__global__ __launch_bounds__(256) void k_prep(const float* __restrict__ phi,
                                              const float* __restrict__ w1,
                                              const float* __restrict__ w2,
                                              const float* __restrict__ w3) {
    int blk = blockIdx.x;
    int tid = threadIdx.x;
    if (blk < NC) {
        __shared__ float red[256];
        int c = blk;
        float s = 0.f;
        for (int d = tid; d < 192; d += 256) s += fabsf(phi[d*NC + c]);
        red[tid] = s;
        __syncthreads();
        for (int off = 128; off; off >>= 1) {
            if (tid < off) red[tid] += red[tid + off];
            __syncthreads();
        }
        float l1 = red[0] + 1e-12f;
        if (tid == 0) g_l1[c] = l1;
        for (int i = tid; i < 16*C1; i += 256) {
            int kk = i / C1, co = i % C1;
            g_wl1h[(c*16 + kk)*C1 + co] = __float2half(l1 * w1[(c*C1 + co)*16 + kk]);
        }
    } else if (blk < NC + W2H_BLKS) {
        int e = (blk - NC)*256 + tid;
        if (e < 9*NTC*C1P) {
            int c1 = e % C1P;
            int t  = e / C1P;
            int c2 = t % NTC;
            int dd = t / NTC;
            int dy = dd / 3, dx = dd % 3;
            float v = (c1 < C1 && c2 < C2) ? w2[((c1*C2 + c2)*3 + dy)*3 + dx] : 0.f;
            g_w2h[e] = __float2half(v);
        }
    } else {
        int e = (blk - NC - W2H_BLKS)*256 + tid;
        if (e < 9*C2*3) {
            int c3 = e % 3;
            int t  = e / 3;
            int c1 = t % C2;
            int dd = t / C2;
            int dy = dd / 3, dx = dd % 3;
            g_w3m[e] = w3[((c1*3 + c3)*3 + dy)*3 + dx];
        }
    }
}

// ---------------- fused transpose + top-30 + saturation ----------------
#define TOPK_SMEM ((NC*33 + NC)*4)
__global__ __launch_bounds__(256) void k_topk(const float* __restrict__ x,
                                              const float* __restrict__ jump_ptr) {
    extern __shared__ float sm[];
    float* sx  = sm;            // [500][33]
    float* sl1 = sm + NC*33;    // [500]

    int b   = blockIdx.y;
    int hw0 = blockIdx.x * 32;
    int tid = threadIdx.x;
    const float* xb = x + ((size_t)b*NC)*HW + hw0;

    for (int i = tid; i < NC*8; i += 256) {
        int c = i >> 3, j = i & 7;
        float4 v = *(const float4*)(xb + c*HW + j*4);
        float* d = sx + c*33 + j*4;
        d[0] = v.x; d[1] = v.y; d[2] = v.z; d[3] = v.w;
    }
    for (int i = tid; i < NC; i += 256) sl1[i] = g_l1[i];
    __syncthreads();

    float jump = *jump_ptr;
    int wid = tid >> 5, lane = tid & 31;

    for (int q = 0; q < 4; q++) {
        int p   = wid*4 + q;
        int pix = b*HW + hw0 + p;

        unsigned u[16];
        #pragma unroll
        for (int t = 0; t < 16; t++) {
            int c = lane + t*32;
            u[t] = (c < NC) ? (__float_as_uint(sx[c*33 + p]) & 0x7fffffffu) : 0u;
        }

        int n = 0;
        for (int it = 0; it < 30; it++) {
            unsigned a0 = max(u[0], u[1]),  a1 = max(u[2], u[3]);
            unsigned a2 = max(u[4], u[5]),  a3 = max(u[6], u[7]);
            unsigned a4 = max(u[8], u[9]),  a5 = max(u[10], u[11]);
            unsigned a6 = max(u[12], u[13]), a7 = max(u[14], u[15]);
            unsigned b0 = max(a0, a1), b1 = max(a2, a3);
            unsigned b2 = max(a4, a5), b3 = max(a6, a7);
            unsigned lm = max(max(b0, b1), max(b2, b3));

            unsigned gm = __reduce_max_sync(0xffffffffu, lm);
            unsigned ball = __ballot_sync(0xffffffffu, lm == gm);
            int leader = __ffs(ball) - 1;
            int c_sel = 0;
            if (lane == leader) {
                int mi = 0;
                #pragma unroll
                for (int t = 15; t >= 0; t--)
                    if (u[t] == gm) { mi = t; u[t] = 0u; }
                c_sel = lane + mi*32;
            }
            c_sel = __shfl_sync(0xffffffffu, c_sel, leader);

            float xv = sx[c_sel*33 + p];
            float th = jump * sl1[c_sel];
            float coef = 0.5f * ((float)((xv > th) - (xv < th)) +
                                 (float)((xv > -th) - (xv < -th)));
            if (coef != 0.f) {
                if (lane == 0) {
                    g_selc[pix*30 + n] = (short)c_sel;
                    g_self[pix*30 + n] = coef;
                }
                n++;
            }
        }
        if (lane == 0) g_seln[pix] = n;
    }
}

// ---------------- conv1 (sparse gather, fp16 table) -> y1h fp16 NHWC/320 ----------------
__global__ __launch_bounds__(160) void k_conv1(const float* __restrict__ b1) {
    __shared__ int   s_cnt;
    __shared__ int   s_pix[4], s_kk[4], s_n[4];
    __shared__ short s_ch[4][32];
    __shared__ float s_cf[4][32];

    int b   = blockIdx.y;
    int oy  = blockIdx.x / 34;
    int ox  = blockIdx.x % 34;
    int tid = threadIdx.x;

    if (tid == 0) {
        int cnt = 0;
        int p = oy & 1, q = ox & 1;
        for (int kh = p; kh < 4; kh += 2) {
            int iy2 = oy - kh; if (iy2 < 0) continue;
            int iy = iy2 >> 1; if (iy >= HWD) continue;
            for (int kw = q; kw < 4; kw += 2) {
                int ix2 = ox - kw; if (ix2 < 0) continue;
                int ix = ix2 >> 1; if (ix >= HWD) continue;
                int pix = (b*HWD + iy)*HWD + ix;
                s_pix[cnt] = pix;
                s_kk[cnt]  = kh*4 + kw;
                s_n[cnt]   = g_seln[pix];
                cnt++;
            }
        }
        s_cnt = cnt;
    }
    __syncthreads();
    int cnt = s_cnt;
    if (tid < 128) {
        int s = tid >> 5, t = tid & 31;
        if (s < cnt && t < s_n[s]) {
            s_ch[s][t] = g_selc[s_pix[s]*30 + t];
            s_cf[s][t] = g_self[s_pix[s]*30 + t];
        }
    }
    __syncthreads();

    size_t obase = ((size_t)(b*1156 + oy*34 + ox))*C1P;
    int t2 = tid;
    if (t2 < 150) {
        float ax0 = 0.f, ay0 = 0.f, ax1 = 0.f, ay1 = 0.f;
        const __half2* wtab = (const __half2*)g_wl1h;
        for (int s = 0; s < cnt; s++) {
            int kk = s_kk[s];
            int ns = s_n[s];
            int t = 0;
            #pragma unroll 2
            for (; t + 1 < ns; t += 2) {
                int ca = (int)s_ch[s][t];
                int cb = (int)s_ch[s][t+1];
                float cfa = s_cf[s][t];
                float cfb = s_cf[s][t+1];
                float2 wa = __half22float2(wtab[(ca*16 + kk)*150 + t2]);
                float2 wb = __half22float2(wtab[(cb*16 + kk)*150 + t2]);
                ax0 = fmaf(cfa, wa.x, ax0);
                ay0 = fmaf(cfa, wa.y, ay0);
                ax1 = fmaf(cfb, wb.x, ax1);
                ay1 = fmaf(cfb, wb.y, ay1);
            }
            if (t < ns) {
                int ca = (int)s_ch[s][t];
                float cfa = s_cf[s][t];
                float2 wa = __half22float2(wtab[(ca*16 + kk)*150 + t2]);
                ax0 = fmaf(cfa, wa.x, ax0);
                ay0 = fmaf(cfa, wa.y, ay0);
            }
        }
        int co = 2*t2;
        float ox2 = fmaxf((ax0 + ax1) + b1[co],   0.f);
        float oy2 = fmaxf((ay0 + ay1) + b1[co+1], 0.f);
        ((__half2*)(g_y1h + obase))[t2] = __floats2half2_rn(ox2, oy2);
    } else {
        ((__half2*)(g_y1h + obase))[t2] = __floats2half2_rn(0.f, 0.f);
    }
}

// ---------------- conv2: fp16 HMMA implicit GEMM, M32xN64 warp tiles -------
// M=128 pixels/CTA, N=128 (c2 padded), K = 9 slabs * 320 ch, chunks of 64
// 3-stage cp.async pipeline; issue() BEFORE compute() so DMA overlaps MMA.
#define STAGE_BYTES 32768
__global__ __launch_bounds__(256, 2) void k_conv2_mma(const float* __restrict__ b2) {
    extern __shared__ char dsm[];
    uint32_t smu = smem_u32(dsm);

    int tid = threadIdx.x;
    int wid = tid >> 5;
    int lane = tid & 31;
    int mg = wid >> 1;        // 0..3 : rows mg*32..+32
    int ng = wid & 1;         // 0..1 : cols ng*64..+64
    int b  = blockIdx.y;
    int p0 = blockIdx.x * 128;

    // ---- hoisted per-thread cp.async geometry (loop-invariant) ----
    int jj = tid & 7;
    int rr = tid >> 3;
    int oyk[4], oxk[4], gbase[4];
    uint32_t dstk[4];
    bool pok[4];
    #pragma unroll
    for (int k = 0; k < 4; k++) {
        int r = rr + k*32;
        int p = p0 + r;
        int oy = p / 36, ox = p - oy*36;
        oyk[k] = oy; oxk[k] = ox;
        pok[k] = (p < 1296);
        gbase[k] = ((b*34 + oy)*34 + ox)*C1P + jj*8;
        dstk[k]  = SWZ128(r*128 + jj*16);
    }

    float acc[2][8][4];
    #pragma unroll
    for (int mt = 0; mt < 2; mt++)
        #pragma unroll
        for (int nt = 0; nt < 8; nt++)
            #pragma unroll
            for (int j = 0; j < 4; j++) acc[mt][nt][j] = 0.f;

    int arow0 = mg*32 +      (lane & 15);
    int arow1 = mg*32 + 16 + (lane & 15);
    int acolb = (lane >> 4) * 16;
    int bn  = (lane & 7) + ((lane >> 4) & 1) * 8;
    int bkb = ((lane >> 3) & 1) * 16;

    auto issue = [&](int i) {
        int s = i % 3;
        int slab = i / 5;
        int c0 = (i - slab*5) * 64;
        int dy = slab / 3, dx = slab - dy*3;
        int shift = (dy*34 + dx)*C1P - c0;
        uint32_t abase = smu + (uint32_t)s * STAGE_BYTES;
        uint32_t bbase = abase + 16384u;
        #pragma unroll
        for (int k = 0; k < 4; k++) {
            bool val = pok[k] & (oyk[k] >= dy) & (oyk[k] < 34 + dy)
                              & (oxk[k] >= dx) & (oxk[k] < 34 + dx);
            size_t goff = val ? (size_t)(gbase[k] - shift) : 0;
            cpa16(abase + dstk[k], g_y1h + goff, val ? 16 : 0);
        }
        const __half* wbase = g_w2h + slab*(NTC*C1P) + c0 + jj*8;
        #pragma unroll
        for (int k = 0; k < 4; k++)
            cpa16(bbase + dstk[k], wbase + (rr + k*32)*C1P, 16);
        cpa_commit();
    };

    auto compute = [&](int s) {
        uint32_t abase = smu + (uint32_t)s * STAGE_BYTES;
        uint32_t bbase = abase + 16384u;
        #pragma unroll
        for (int ks = 0; ks < 4; ks++) {
            uint32_t a0[4], a1[4];
            ldsm4(a0, abase + SWZ128(arow0*128 + ks*32 + acolb));
            ldsm4(a1, abase + SWZ128(arow1*128 + ks*32 + acolb));
            #pragma unroll
            for (int nt = 0; nt < 4; nt++) {
                uint32_t bf[4];
                ldsm4(bf, bbase + SWZ128((ng*64 + nt*16 + bn)*128 + ks*32 + bkb));
                mma16816(acc[0][nt*2],     a0, bf[0], bf[1]);
                mma16816(acc[0][nt*2 + 1], a0, bf[2], bf[3]);
                mma16816(acc[1][nt*2],     a1, bf[0], bf[1]);
                mma16816(acc[1][nt*2 + 1], a1, bf[2], bf[3]);
            }
        }
    };

    issue(0);
    issue(1);
    for (int i = 0; i < 45; i++) {
        if (i <= 43) asm volatile("cp.async.wait_group 1;" ::: "memory");
        else         asm volatile("cp.async.wait_group 0;" ::: "memory");
        __syncthreads();
        if (i <= 42) issue(i + 2);   // DMA for chunk i+2 overlaps compute(i)
        compute(i % 3);
    }

    // epilogue: bias + relu + store fp16 NHWC
    int g  = lane >> 2;
    int qp = (lane & 3) * 2;
    #pragma unroll
    for (int mt = 0; mt < 2; mt++) {
        int rbase = p0 + mg*32 + mt*16 + g;
        #pragma unroll
        for (int nt = 0; nt < 8; nt++) {
            int n = ng*64 + nt*8 + qp;
            if (n < 100) {
                float b0v = b2[n], b1v = b2[n + 1];
                if (rbase < 1296) {
                    float o0 = fmaxf(acc[mt][nt][0] + b0v, 0.f);
                    float o1 = fmaxf(acc[mt][nt][1] + b1v, 0.f);
                    *(__half2*)&g_y2h[((size_t)b*1296 + rbase)*C2 + n] =
                        __floats2half2_rn(o0, o1);
                }
                if (rbase + 8 < 1296) {
                    float o0 = fmaxf(acc[mt][nt][2] + b0v, 0.f);
                    float o1 = fmaxf(acc[mt][nt][3] + b1v, 0.f);
                    *(__half2*)&g_y2h[((size_t)b*1296 + rbase + 8)*C2 + n] =
                        __floats2half2_rn(o0, o1);
                }
            }
        }
    }
}

// ---------------- conv3 (100->3 3x3 transpose) + ReLU + center crop -------
#define CONV3_SMEM ((3*35*100 + 9*C2*3)*4)
__global__ __launch_bounds__(96) void k_conv3(const float* __restrict__ b3,
                                              float* __restrict__ out) {
    extern __shared__ float cs[];
    float* s_y2 = cs;                 // [3][35][100] f32
    float* s_w3 = cs + 3*35*100;      // [c3][dy][dx][100]

    int u   = blockIdx.x;
    int b   = blockIdx.y;
    int tid = threadIdx.x;
    int v   = tid % 32;
    int c3  = tid / 32;

    for (int i = tid; i < 9*C2*3; i += 96) {
        int c1 = i % C2;
        int t  = i / C2;
        int dd = t % 9;
        int cc = t / 9;
        s_w3[(cc*9 + dd)*C2 + c1] = g_w3m[(dd*C2 + c1)*3 + cc];
    }
    {
        const __half2* src = (const __half2*)g_y2h;
        for (int i = tid; i < 3*35*50; i += 96) {
            int cl = i % 50;
            int t  = i / 50;
            int ix = t % 35;
            int r  = t / 35;
            float2 vv = __half22float2(
                src[(((size_t)b*1296 + (u+1+r)*36 + (ix+1))*C2 >> 1) + cl]);
            s_y2[(r*35 + ix)*100 + cl*2]     = vv.x;
            s_y2[(r*35 + ix)*100 + cl*2 + 1] = vv.y;
        }
    }
    __syncthreads();

    float acc = 0.f;
    #pragma unroll
    for (int dy = 0; dy < 3; dy++) {
        int r = 2 - dy;
        #pragma unroll
        for (int dx = 0; dx < 3; dx++) {
            int col = v + 2 - dx;
            const float4* yrow = (const float4*)(s_y2 + (r*35 + col)*100);
            const float4* wrow = (const float4*)(s_w3 + (c3*9 + dy*3 + dx)*C2);
            #pragma unroll 5
            for (int c = 0; c < 25; c++) {
                float4 yv = yrow[c];
                float4 wv = wrow[c];
                acc = fmaf(yv.x, wv.x, acc);
                acc = fmaf(yv.y, wv.y, acc);
                acc = fmaf(yv.z, wv.z, acc);
                acc = fmaf(yv.w, wv.w, acc);
            }
        }
    }
    out[((b*3 + c3)*32 + u)*32 + v] = fmaxf(acc + b3[c3], 0.f);
}

// ---------------- launch ----------------
extern "C" void kernel_launch(void* const* d_in, const int* in_sizes, int n_in,
                              void* d_out, int out_size) {
    const float* x    = (const float*)d_in[0];
    const float* phi  = (const float*)d_in[1];
    const float* jump = (const float*)d_in[2];
    const float* w1   = (const float*)d_in[3];
    const float* b1   = (const float*)d_in[4];
    const float* w2   = (const float*)d_in[5];
    const float* b2   = (const float*)d_in[6];
    const float* w3   = (const float*)d_in[7];
    const float* b3   = (const float*)d_in[8];
    float* out = (float*)d_out;

    cudaFuncSetAttribute(k_conv2_mma, cudaFuncAttributeMaxDynamicSharedMemorySize,
                         3*STAGE_BYTES);
    cudaFuncSetAttribute(k_topk, cudaFuncAttributeMaxDynamicSharedMemorySize,
                         TOPK_SMEM);
    cudaFuncSetAttribute(k_conv3, cudaFuncAttributeMaxDynamicSharedMemorySize,
                         CONV3_SMEM);

    k_prep<<<NC + W2H_BLKS + W3M_BLKS, 256>>>(phi, w1, w2, w3);   // 0
    k_topk<<<dim3(8, NB), 256, TOPK_SMEM>>>(x, jump);             // 1
    k_conv1<<<dim3(34*34, NB), 160>>>(b1);                        // 2
    k_conv2_mma<<<dim3(11, NB), 256, 3*STAGE_BYTES>>>(b2);        // 3  <- profiled slot
    k_conv3<<<dim3(32, NB), 96, CONV3_SMEM>>>(b3, out);           // 4
}